// round 4
// baseline (speedup 1.0000x reference)
#include <cuda_runtime.h>
#include <math.h>

#define NN   4096
#define DD   256
#define HHE  4
#define DHH  64
#define EE   131072
#define DEGE 32
#define FF   1024

// ---------------- scratch (no allocations allowed) ----------------
__device__ float g_q[NN * DD];
__device__ float g_k[NN * DD];
__device__ float g_v[NN * DD];
__device__ float g_attn[NN * DD];
__device__ float g_t[NN * DD];
__device__ float g_h1[NN * DD];
__device__ float g_act[NN * FF];
__device__ int   g_dst[EE];
__device__ int   g_is64;

// ---------------- dst dtype sniff + normalize ---------------------
// Reference declares dst as int64 but JAX w/o x64 downgrades to int32.
// Detect at runtime: int64 little-endian with values < 2^31 has ALL odd
// 32-bit words == 0; int32 has random dst values there. Deterministic.
__global__ void detect_dst_kernel(const int* __restrict__ dst_raw) {
    __shared__ int any_nonzero;
    if (threadIdx.x == 0) any_nonzero = 0;
    __syncthreads();
    for (int i = threadIdx.x; i < 2048; i += blockDim.x)
        if (dst_raw[2 * i + 1] != 0) any_nonzero = 1;
    __syncthreads();
    if (threadIdx.x == 0) g_is64 = (any_nonzero == 0);
}

__global__ void normalize_dst_kernel(const int* __restrict__ dst_raw) {
    const int is64 = g_is64;
    int i = blockIdx.x * blockDim.x + threadIdx.x;
    if (i < EE) g_dst[i] = is64 ? dst_raw[2 * i] : dst_raw[i];
}

// ---------------- GEMM core: C[M,N] = A[M,K] * B[N,K]^T + bias ----
// BM=128, BN=64, BK=16, 256 threads, 8x4 per-thread microtile.
template <bool RELU>
__device__ __forceinline__ void gemm_tile(
    const float* __restrict__ A, const float* __restrict__ B,
    const float* __restrict__ bias, float* __restrict__ C,
    int N, int K, int row0, int col0)
{
    constexpr int BK = 16;
    __shared__ float As[BK][128 + 4];
    __shared__ float Bs[BK][64 + 4];

    const int tid = threadIdx.x;
    const int tx = tid & 15;   // 0..15 -> 4 cols each
    const int ty = tid >> 4;   // 0..15 -> 8 rows each

    const int lr = tid >> 2;          // 0..63
    const int lc = (tid & 3) << 2;    // 0,4,8,12

    const float* Aptr  = A + (size_t)(row0 + lr) * K + lc;
    const float* Aptr2 = A + (size_t)(row0 + lr + 64) * K + lc;
    const float* Bptr  = B + (size_t)(col0 + lr) * K + lc;

    float acc[8][4];
#pragma unroll
    for (int i = 0; i < 8; i++)
#pragma unroll
        for (int j = 0; j < 4; j++) acc[i][j] = 0.f;

    for (int k0 = 0; k0 < K; k0 += BK) {
        float4 a0 = *(const float4*)(Aptr  + k0);
        float4 a1 = *(const float4*)(Aptr2 + k0);
        float4 b0 = *(const float4*)(Bptr  + k0);

        As[lc + 0][lr] = a0.x; As[lc + 1][lr] = a0.y;
        As[lc + 2][lr] = a0.z; As[lc + 3][lr] = a0.w;
        As[lc + 0][lr + 64] = a1.x; As[lc + 1][lr + 64] = a1.y;
        As[lc + 2][lr + 64] = a1.z; As[lc + 3][lr + 64] = a1.w;
        Bs[lc + 0][lr] = b0.x; Bs[lc + 1][lr] = b0.y;
        Bs[lc + 2][lr] = b0.z; Bs[lc + 3][lr] = b0.w;
        __syncthreads();

#pragma unroll
        for (int kk = 0; kk < BK; kk++) {
            float4 alo = *(const float4*)&As[kk][ty * 8];
            float4 ahi = *(const float4*)&As[kk][ty * 8 + 4];
            float4 bb  = *(const float4*)&Bs[kk][tx * 4];
            float ar[8] = {alo.x, alo.y, alo.z, alo.w, ahi.x, ahi.y, ahi.z, ahi.w};
            float br[4] = {bb.x, bb.y, bb.z, bb.w};
#pragma unroll
            for (int i = 0; i < 8; i++)
#pragma unroll
                for (int j = 0; j < 4; j++)
                    acc[i][j] = fmaf(ar[i], br[j], acc[i][j]);
        }
        __syncthreads();
    }

    float4 b4 = *(const float4*)(bias + col0 + tx * 4);
#pragma unroll
    for (int i = 0; i < 8; i++) {
        float4 o;
        o.x = acc[i][0] + b4.x;
        o.y = acc[i][1] + b4.y;
        o.z = acc[i][2] + b4.z;
        o.w = acc[i][3] + b4.w;
        if (RELU) {
            o.x = fmaxf(o.x, 0.f); o.y = fmaxf(o.y, 0.f);
            o.z = fmaxf(o.z, 0.f); o.w = fmaxf(o.w, 0.f);
        }
        *(float4*)(C + (size_t)(row0 + ty * 8 + i) * N + col0 + tx * 4) = o;
    }
}

__global__ void __launch_bounds__(256, 2) gemm_bias_kernel(
    const float* __restrict__ A, const float* __restrict__ B,
    const float* __restrict__ bias, float* __restrict__ C,
    int N, int K)
{
    gemm_tile<false>(A, B, bias, C, N, K, blockIdx.y * 128, blockIdx.x * 64);
}

__global__ void __launch_bounds__(256, 2) gemm_bias_relu_kernel(
    const float* __restrict__ A, const float* __restrict__ B,
    const float* __restrict__ bias, float* __restrict__ C,
    int N, int K)
{
    gemm_tile<true>(A, B, bias, C, N, K, blockIdx.y * 128, blockIdx.x * 64);
}

// Fused QKV: blockIdx.z selects projection. 384 blocks in one launch
// instead of 3 serialized 128-block launches (fills the 148-SM chip).
__global__ void __launch_bounds__(256, 2) qkv_gemm_kernel(
    const float* __restrict__ A,
    const float* __restrict__ Wq, const float* __restrict__ bq, float* __restrict__ q,
    const float* __restrict__ Wk, const float* __restrict__ bk, float* __restrict__ k,
    const float* __restrict__ Wv, const float* __restrict__ bv, float* __restrict__ v)
{
    const float* B;  const float* bias;  float* C;
    if (blockIdx.z == 0)      { B = Wq; bias = bq; C = q; }
    else if (blockIdx.z == 1) { B = Wk; bias = bk; C = k; }
    else                      { B = Wv; bias = bv; C = v; }
    gemm_tile<false>(A, B, bias, C, DD, DD, blockIdx.y * 128, blockIdx.x * 64);
}

// ---------------- sparse masked attention -------------------------
// One block per node (128 threads); warp w handles head w.
// Lane i owns edge i of the node. Dedup: duplicate dst -> LAST edge wins
// (matches in-order scatter .at[src,dst].set(ew)).
__global__ void __launch_bounds__(128) attn_kernel(
    const float* __restrict__ q, const float* __restrict__ k,
    const float* __restrict__ v, const float* __restrict__ ew,
    const int* __restrict__ dst, float* __restrict__ out)
{
    const unsigned FULL = 0xffffffffu;
    const int n    = blockIdx.x;
    const int head = threadIdx.x >> 5;
    const int lane = threadIdx.x & 31;

    const int   e   = n * DEGE + lane;
    const int   d_i = dst[e];
    const float w_i = fmaxf(ew[e], 0.f);

    // dedup (last occurrence wins)
    bool valid = true;
#pragma unroll
    for (int j = 1; j < 32; j++) {
        int dj = __shfl_sync(FULL, d_i, (lane + j) & 31);
        if (lane + j < 32 && dj == d_i) valid = false;
    }

    const float* qrow = q + (size_t)n * DD + head * DHH;
    const float q0 = qrow[lane];
    const float q1 = qrow[lane + 32];

    // scores: s_i = q . k[dst_i] / 8 + ew_i  (valid keys only)
    float myscore = -INFINITY;
#pragma unroll 4
    for (int i = 0; i < 32; i++) {
        int di = __shfl_sync(FULL, d_i, i);
        const float* krow = k + (size_t)di * DD + head * DHH;
        float p = q0 * krow[lane] + q1 * krow[lane + 32];
#pragma unroll
        for (int s = 16; s > 0; s >>= 1) p += __shfl_xor_sync(FULL, p, s);
        if (lane == i) myscore = p;
    }
    myscore = valid ? (myscore * 0.125f + w_i) : -INFINITY;

    // softmax over valid lanes
    float m = myscore;
#pragma unroll
    for (int s = 16; s > 0; s >>= 1) m = fmaxf(m, __shfl_xor_sync(FULL, m, s));
    float p = valid ? __expf(myscore - m) : 0.f;
    float den = p;
#pragma unroll
    for (int s = 16; s > 0; s >>= 1) den += __shfl_xor_sync(FULL, den, s);
    const float wgt = p / den;

    // out[n, head, :] = sum_i wgt_i * v[dst_i, head, :]
    float o0 = 0.f, o1 = 0.f;
#pragma unroll 4
    for (int i = 0; i < 32; i++) {
        float wi = __shfl_sync(FULL, wgt, i);
        int   di = __shfl_sync(FULL, d_i, i);
        const float* vrow = v + (size_t)di * DD + head * DHH;
        o0 = fmaf(wi, vrow[lane],      o0);
        o1 = fmaf(wi, vrow[lane + 32], o1);
    }
    out[(size_t)n * DD + head * DHH + lane]      = o0;
    out[(size_t)n * DD + head * DHH + 32 + lane] = o1;
}

// ---------------- residual add + LayerNorm (one block per row) ----
__global__ void __launch_bounds__(256) add_ln_kernel(
    const float* __restrict__ x, const float* __restrict__ res,
    const float* __restrict__ g, const float* __restrict__ b,
    float* __restrict__ out)
{
    const unsigned FULL = 0xffffffffu;
    const int row = blockIdx.x;
    const int t   = threadIdx.x;

    float v = x[(size_t)row * DD + t] + res[(size_t)row * DD + t];
    float s = v, ss = v * v;
#pragma unroll
    for (int o = 16; o > 0; o >>= 1) {
        s  += __shfl_xor_sync(FULL, s,  o);
        ss += __shfl_xor_sync(FULL, ss, o);
    }
    __shared__ float sh_s[8], sh_ss[8];
    const int w = t >> 5, l = t & 31;
    if (l == 0) { sh_s[w] = s; sh_ss[w] = ss; }
    __syncthreads();
    float S = 0.f, SS = 0.f;
#pragma unroll
    for (int i = 0; i < 8; i++) { S += sh_s[i]; SS += sh_ss[i]; }
    const float mean = S * (1.0f / DD);
    const float var  = SS * (1.0f / DD) - mean * mean;
    const float inv  = rsqrtf(var + 1e-5f);
    out[(size_t)row * DD + t] = (v - mean) * inv * g[t] + b[t];
}

// ---------------- launch ------------------------------------------
extern "C" void kernel_launch(void* const* d_in, const int* in_sizes, int n_in,
                              void* d_out, int out_size)
{
    const float* h    = (const float*)d_in[0];
    const float* ew   = (const float*)d_in[1];
    // d_in[2] = src (unused: src[e] == e / DEG by construction)
    const int*   dstR = (const int*)d_in[3];
    const float* Wq   = (const float*)d_in[4];
    const float* bq   = (const float*)d_in[5];
    const float* Wk   = (const float*)d_in[6];
    const float* bk   = (const float*)d_in[7];
    const float* Wv   = (const float*)d_in[8];
    const float* bv   = (const float*)d_in[9];
    const float* Wo   = (const float*)d_in[10];
    const float* bo   = (const float*)d_in[11];
    const float* W1   = (const float*)d_in[12];
    const float* b1   = (const float*)d_in[13];
    const float* W2   = (const float*)d_in[14];
    const float* b2   = (const float*)d_in[15];
    const float* l1g  = (const float*)d_in[16];
    const float* l1b  = (const float*)d_in[17];
    const float* l2g  = (const float*)d_in[18];
    const float* l2b  = (const float*)d_in[19];

    float *q, *k, *v, *attn, *t, *h1, *act;
    int *dstN;
    cudaGetSymbolAddress((void**)&q,    g_q);
    cudaGetSymbolAddress((void**)&k,    g_k);
    cudaGetSymbolAddress((void**)&v,    g_v);
    cudaGetSymbolAddress((void**)&attn, g_attn);
    cudaGetSymbolAddress((void**)&t,    g_t);
    cudaGetSymbolAddress((void**)&h1,   g_h1);
    cudaGetSymbolAddress((void**)&act,  g_act);
    cudaGetSymbolAddress((void**)&dstN, g_dst);

    // normalize dst to int32 regardless of harness int32/int64 layout
    detect_dst_kernel<<<1, 256>>>(dstR);
    normalize_dst_kernel<<<EE / 256, 256>>>(dstR);

    dim3 gQKV(DD / 64, NN / 128, 3);  // fused Q,K,V: 384 blocks
    dim3 gD(DD / 64, NN / 128);       // N=256 GEMMs: 128 blocks
    dim3 gF(FF / 64, NN / 128);       // N=1024 GEMM: 512 blocks

    qkv_gemm_kernel<<<gQKV, 256>>>(h, Wq, bq, q, Wk, bk, k, Wv, bv, v);

    attn_kernel<<<NN, 128>>>(q, k, v, ew, dstN, attn);

    gemm_bias_kernel<<<gD, 256>>>(attn, Wo, bo, t, DD, DD);
    add_ln_kernel<<<NN, 256>>>(t, h, l1g, l1b, h1);

    gemm_bias_relu_kernel<<<gF, 256>>>(h1, W1, b1, act, FF, DD);
    gemm_bias_kernel<<<gD, 256>>>(act, W2, b2, t, DD, FF);
    add_ln_kernel<<<NN, 256>>>(t, h1, l2g, l2b, (float*)d_out);
}

// round 7
// speedup vs baseline: 1.3496x; 1.3496x over previous
#include <cuda_runtime.h>
#include <cuda_bf16.h>
#include <mma.h>
#include <math.h>
#include <stdint.h>

using namespace nvcuda;

#define NN   4096
#define DD   256
#define HHE  4
#define DHH  64
#define EE   131072
#define DEGE 32
#define FF   1024

// ---------------- scratch (no allocations allowed) ----------------
__device__ __nv_bfloat16 g_w_hi[786432];   // Wq|Wk|Wv|Wo|W1|W2
__device__ __nv_bfloat16 g_w_lo[786432];
__device__ __nv_bfloat16 g_h_hi[NN * DD];
__device__ __nv_bfloat16 g_h_lo[NN * DD];
__device__ float         g_qkv[3 * NN * DD];
__device__ __nv_bfloat16 g_attn_hi[NN * DD];
__device__ __nv_bfloat16 g_attn_lo[NN * DD];
__device__ float         g_t[NN * DD];
__device__ float         g_h1[NN * DD];
__device__ __nv_bfloat16 g_h1_hi[NN * DD];
__device__ __nv_bfloat16 g_h1_lo[NN * DD];
__device__ __nv_bfloat16 g_act_hi[NN * FF];
__device__ __nv_bfloat16 g_act_lo[NN * FF];
__device__ int           g_dst[EE];
__device__ int           g_is64;

// weight offsets in g_w_*
#define WQ_OFF 0
#define WK_OFF 65536
#define WV_OFF 131072
#define WO_OFF 196608
#define W1_OFF 262144
#define W2_OFF 524288

// ---------------- dst dtype sniff + normalize ---------------------
__global__ void detect_dst_kernel(const int* __restrict__ dst_raw) {
    __shared__ int any_nonzero;
    if (threadIdx.x == 0) any_nonzero = 0;
    __syncthreads();
    for (int i = threadIdx.x; i < 2048; i += blockDim.x)
        if (dst_raw[2 * i + 1] != 0) any_nonzero = 1;
    __syncthreads();
    if (threadIdx.x == 0) g_is64 = (any_nonzero == 0);
}
__global__ void normalize_dst_kernel(const int* __restrict__ dst_raw) {
    const int is64 = g_is64;
    int i = blockIdx.x * blockDim.x + threadIdx.x;
    if (i < EE) g_dst[i] = is64 ? dst_raw[2 * i] : dst_raw[i];
}

// ---------------- fp32 -> bf16 hi/lo split ------------------------
__global__ void split_kernel(const float* __restrict__ x,
                             __nv_bfloat16* __restrict__ hi,
                             __nv_bfloat16* __restrict__ lo, int n) {
    int i = (blockIdx.x * 256 + threadIdx.x) * 4;
    if (i >= n) return;
    float4 v = *(const float4*)(x + i);
    __nv_bfloat16 h0 = __float2bfloat16(v.x), h1 = __float2bfloat16(v.y);
    __nv_bfloat16 h2 = __float2bfloat16(v.z), h3 = __float2bfloat16(v.w);
    __nv_bfloat16 l0 = __float2bfloat16(v.x - __bfloat162float(h0));
    __nv_bfloat16 l1 = __float2bfloat16(v.y - __bfloat162float(h1));
    __nv_bfloat16 l2 = __float2bfloat16(v.z - __bfloat162float(h2));
    __nv_bfloat16 l3 = __float2bfloat16(v.w - __bfloat162float(h3));
    *(__nv_bfloat162*)(hi + i)     = __nv_bfloat162(h0, h1);
    *(__nv_bfloat162*)(hi + i + 2) = __nv_bfloat162(h2, h3);
    *(__nv_bfloat162*)(lo + i)     = __nv_bfloat162(l0, l1);
    *(__nv_bfloat162*)(lo + i + 2) = __nv_bfloat162(l2, l3);
}

// ================= WMMA bf16 GEMM (portable HMMA path) ============
// C[M,Nc] = A[M,K] * B[Nc,K]^T + bias, split-bf16 3-term precision:
//   C ~= Ahi*Bhi + Ahi*Blo + Alo*Bhi  (residual ~2^-18)
// BM=128, BN=64, BK=32, 256 thr = 8 warps (4Mx2N), 32x32 per warp.
#define LDA 40   // bf16 SMEM stride (32 + 8 pad), mult of 8
#define LDC 68   // f32 epilogue stride, mult of 4
#define SM_A_HI 0
#define SM_A_LO (128 * LDA)
#define SM_B_HI (2 * 128 * LDA)
#define SM_B_LO (2 * 128 * LDA + 64 * LDA)
#define SM_BYTES (128 * LDC * 4)   // 34816 (>= bf16 region 30720), reused for C

template <int MODE>  // 0: fp32 C out; 1: relu + bf16 hi/lo out
__device__ __forceinline__ void gemm_wmma_body(
    const __nv_bfloat16* __restrict__ Ahi, const __nv_bfloat16* __restrict__ Alo,
    const __nv_bfloat16* __restrict__ Bhi, const __nv_bfloat16* __restrict__ Blo,
    const float* __restrict__ bias, float* __restrict__ C,
    __nv_bfloat16* __restrict__ Ohi, __nv_bfloat16* __restrict__ Olo,
    int Nc, int K, int row0, int col0)
{
    extern __shared__ char smem[];
    __nv_bfloat16* sAh = (__nv_bfloat16*)smem + SM_A_HI;
    __nv_bfloat16* sAl = (__nv_bfloat16*)smem + SM_A_LO;
    __nv_bfloat16* sBh = (__nv_bfloat16*)smem + SM_B_HI;
    __nv_bfloat16* sBl = (__nv_bfloat16*)smem + SM_B_LO;
    float* sC = (float*)smem;

    const int tid = threadIdx.x;
    const int wid = tid >> 5;
    const int wm  = wid & 3;   // 0..3 : 32-row band
    const int wn  = wid >> 2;  // 0..1 : 32-col band

    wmma::fragment<wmma::accumulator, 16, 16, 16, float> acc[2][2];
#pragma unroll
    for (int i = 0; i < 2; i++)
#pragma unroll
        for (int j = 0; j < 2; j++) wmma::fill_fragment(acc[i][j], 0.0f);

    const int ar = tid >> 2;            // 0..63
    const int ac = (tid & 3) * 8;       // 0,8,16,24

    for (int kc = 0; kc < K; kc += 32) {
        // A: 128 rows x 32 k  (2 passes of 64 rows)
#pragma unroll
        for (int p = 0; p < 2; p++) {
            const int r = ar + p * 64;
            *(uint4*)&sAh[r * LDA + ac] = *(const uint4*)&Ahi[(size_t)(row0 + r) * K + kc + ac];
            *(uint4*)&sAl[r * LDA + ac] = *(const uint4*)&Alo[(size_t)(row0 + r) * K + kc + ac];
        }
        // B: 64 rows x 32 k
        *(uint4*)&sBh[ar * LDA + ac] = *(const uint4*)&Bhi[(size_t)(col0 + ar) * K + kc + ac];
        *(uint4*)&sBl[ar * LDA + ac] = *(const uint4*)&Blo[(size_t)(col0 + ar) * K + kc + ac];
        __syncthreads();

#pragma unroll
        for (int kk = 0; kk < 32; kk += 16) {
            wmma::fragment<wmma::matrix_a, 16, 16, 16, __nv_bfloat16, wmma::row_major> ah[2], al[2];
            wmma::fragment<wmma::matrix_b, 16, 16, 16, __nv_bfloat16, wmma::col_major> bh[2], bl[2];
#pragma unroll
            for (int i = 0; i < 2; i++) {
                wmma::load_matrix_sync(ah[i], sAh + (wm * 32 + i * 16) * LDA + kk, LDA);
                wmma::load_matrix_sync(al[i], sAl + (wm * 32 + i * 16) * LDA + kk, LDA);
            }
#pragma unroll
            for (int j = 0; j < 2; j++) {
                wmma::load_matrix_sync(bh[j], sBh + (wn * 32 + j * 16) * LDA + kk, LDA);
                wmma::load_matrix_sync(bl[j], sBl + (wn * 32 + j * 16) * LDA + kk, LDA);
            }
#pragma unroll
            for (int i = 0; i < 2; i++)
#pragma unroll
                for (int j = 0; j < 2; j++) {
                    wmma::mma_sync(acc[i][j], ah[i], bh[j], acc[i][j]);
                    wmma::mma_sync(acc[i][j], ah[i], bl[j], acc[i][j]);
                    wmma::mma_sync(acc[i][j], al[i], bh[j], acc[i][j]);
                }
        }
        __syncthreads();
    }

    // park accumulators in SMEM, then elementwise epilogue
#pragma unroll
    for (int i = 0; i < 2; i++)
#pragma unroll
        for (int j = 0; j < 2; j++)
            wmma::store_matrix_sync(sC + (wm * 32 + i * 16) * LDC + wn * 32 + j * 16,
                                    acc[i][j], LDC, wmma::mem_row_major);
    __syncthreads();

    for (int e = tid; e < 128 * 64; e += 256) {
        const int r = e >> 6, c = e & 63;
        float val = sC[r * LDC + c] + bias[col0 + c];
        if (MODE == 0) {
            C[(size_t)(row0 + r) * Nc + col0 + c] = val;
        } else {
            val = fmaxf(val, 0.f);
            __nv_bfloat16 hh = __float2bfloat16(val);
            Ohi[(size_t)(row0 + r) * Nc + col0 + c] = hh;
            Olo[(size_t)(row0 + r) * Nc + col0 + c] =
                __float2bfloat16(val - __bfloat162float(hh));
        }
    }
}

template <int MODE>
__global__ void __launch_bounds__(256, 2)
gemm_wmma_kernel(const __nv_bfloat16* __restrict__ Ahi, const __nv_bfloat16* __restrict__ Alo,
                 const __nv_bfloat16* __restrict__ Bhi, const __nv_bfloat16* __restrict__ Blo,
                 const float* __restrict__ bias, float* __restrict__ C,
                 __nv_bfloat16* __restrict__ Ohi, __nv_bfloat16* __restrict__ Olo,
                 int Nc, int K)
{
    gemm_wmma_body<MODE>(Ahi, Alo, Bhi, Blo, bias, C, Ohi, Olo, Nc, K,
                         blockIdx.y * 128, blockIdx.x * 64);
}

__global__ void __launch_bounds__(256, 2)
qkv_wmma_kernel(const __nv_bfloat16* __restrict__ Ahi, const __nv_bfloat16* __restrict__ Alo,
                const float* __restrict__ bq, const float* __restrict__ bk,
                const float* __restrict__ bv, float* __restrict__ qkv)
{
    const int sel = blockIdx.z;
    const __nv_bfloat16* Bh = g_w_hi + sel * 65536;
    const __nv_bfloat16* Bl = g_w_lo + sel * 65536;
    const float* bias = (sel == 0) ? bq : ((sel == 1) ? bk : bv);
    float* C = qkv + (size_t)sel * NN * DD;
    gemm_wmma_body<0>(Ahi, Alo, Bh, Bl, bias, C, nullptr, nullptr, DD, DD,
                      blockIdx.y * 128, blockIdx.x * 64);
}

// ---------------- sparse masked attention -------------------------
// One block/node (128 thr); warp = head. Lane i owns edge i.
// Duplicate dst -> LAST edge wins (matches in-order scatter).
// Emits bf16 hi/lo split directly (feeds O-proj GEMM).
__global__ void __launch_bounds__(128) attn_kernel(
    const float* __restrict__ q, const float* __restrict__ k,
    const float* __restrict__ v, const float* __restrict__ ew,
    const int* __restrict__ dst,
    __nv_bfloat16* __restrict__ out_hi, __nv_bfloat16* __restrict__ out_lo)
{
    const unsigned FULL = 0xffffffffu;
    const int n    = blockIdx.x;
    const int head = threadIdx.x >> 5;
    const int lane = threadIdx.x & 31;

    const int   e   = n * DEGE + lane;
    const int   d_i = dst[e];
    const float w_i = fmaxf(ew[e], 0.f);

    bool valid = true;
#pragma unroll
    for (int j = 1; j < 32; j++) {
        int dj = __shfl_sync(FULL, d_i, (lane + j) & 31);
        if (lane + j < 32 && dj == d_i) valid = false;
    }

    const float* qrow = q + (size_t)n * DD + head * DHH;
    const float q0 = qrow[lane];
    const float q1 = qrow[lane + 32];

    float myscore = -INFINITY;
#pragma unroll 4
    for (int i = 0; i < 32; i++) {
        int di = __shfl_sync(FULL, d_i, i);
        const float* krow = k + (size_t)di * DD + head * DHH;
        float p = q0 * krow[lane] + q1 * krow[lane + 32];
#pragma unroll
        for (int s = 16; s > 0; s >>= 1) p += __shfl_xor_sync(FULL, p, s);
        if (lane == i) myscore = p;
    }
    myscore = valid ? (myscore * 0.125f + w_i) : -INFINITY;

    float m = myscore;
#pragma unroll
    for (int s = 16; s > 0; s >>= 1) m = fmaxf(m, __shfl_xor_sync(FULL, m, s));
    float p = valid ? __expf(myscore - m) : 0.f;
    float den = p;
#pragma unroll
    for (int s = 16; s > 0; s >>= 1) den += __shfl_xor_sync(FULL, den, s);
    const float wgt = p / den;

    float o0 = 0.f, o1 = 0.f;
#pragma unroll 4
    for (int i = 0; i < 32; i++) {
        float wi = __shfl_sync(FULL, wgt, i);
        int   di = __shfl_sync(FULL, d_i, i);
        const float* vrow = v + (size_t)di * DD + head * DHH;
        o0 = fmaf(wi, vrow[lane],      o0);
        o1 = fmaf(wi, vrow[lane + 32], o1);
    }
    const size_t i0 = (size_t)n * DD + head * DHH + lane;
    __nv_bfloat16 h0 = __float2bfloat16(o0);
    __nv_bfloat16 h1 = __float2bfloat16(o1);
    out_hi[i0]      = h0;
    out_hi[i0 + 32] = h1;
    out_lo[i0]      = __float2bfloat16(o0 - __bfloat162float(h0));
    out_lo[i0 + 32] = __float2bfloat16(o1 - __bfloat162float(h1));
}

// ---------------- residual add + LayerNorm ------------------------
__global__ void __launch_bounds__(256) add_ln_kernel(
    const float* __restrict__ x, const float* __restrict__ res,
    const float* __restrict__ g, const float* __restrict__ b,
    float* __restrict__ out,
    __nv_bfloat16* __restrict__ out_hi, __nv_bfloat16* __restrict__ out_lo)
{
    const unsigned FULL = 0xffffffffu;
    const int row = blockIdx.x;
    const int t   = threadIdx.x;

    float v = x[(size_t)row * DD + t] + res[(size_t)row * DD + t];
    float s = v, ss = v * v;
#pragma unroll
    for (int o = 16; o > 0; o >>= 1) {
        s  += __shfl_xor_sync(FULL, s,  o);
        ss += __shfl_xor_sync(FULL, ss, o);
    }
    __shared__ float sh_s[8], sh_ss[8];
    const int w = t >> 5, l = t & 31;
    if (l == 0) { sh_s[w] = s; sh_ss[w] = ss; }
    __syncthreads();
    float S = 0.f, SS = 0.f;
#pragma unroll
    for (int i = 0; i < 8; i++) { S += sh_s[i]; SS += sh_ss[i]; }
    const float mean = S * (1.0f / DD);
    const float var  = SS * (1.0f / DD) - mean * mean;
    const float inv  = rsqrtf(var + 1e-5f);
    const float y = (v - mean) * inv * g[t] + b[t];
    out[(size_t)row * DD + t] = y;
    if (out_hi) {
        __nv_bfloat16 hh = __float2bfloat16(y);
        out_hi[(size_t)row * DD + t] = hh;
        out_lo[(size_t)row * DD + t] = __float2bfloat16(y - __bfloat162float(hh));
    }
}

// ---------------- launch ------------------------------------------
extern "C" void kernel_launch(void* const* d_in, const int* in_sizes, int n_in,
                              void* d_out, int out_size)
{
    const float* h    = (const float*)d_in[0];
    const float* ew   = (const float*)d_in[1];
    // d_in[2] = src (unused: src[e] == e / DEG by construction)
    const int*   dstR = (const int*)d_in[3];
    const float* Wq   = (const float*)d_in[4];
    const float* bq   = (const float*)d_in[5];
    const float* Wk   = (const float*)d_in[6];
    const float* bk   = (const float*)d_in[7];
    const float* Wv   = (const float*)d_in[8];
    const float* bv   = (const float*)d_in[9];
    const float* Wo   = (const float*)d_in[10];
    const float* bo   = (const float*)d_in[11];
    const float* W1   = (const float*)d_in[12];
    const float* b1   = (const float*)d_in[13];
    const float* W2   = (const float*)d_in[14];
    const float* b2   = (const float*)d_in[15];
    const float* l1g  = (const float*)d_in[16];
    const float* l1b  = (const float*)d_in[17];
    const float* l2g  = (const float*)d_in[18];
    const float* l2b  = (const float*)d_in[19];

    __nv_bfloat16 *whi, *wlo, *hhi, *hlo, *ahi, *alo, *h1hi, *h1lo, *acthi, *actlo;
    float *qkv, *t, *h1;
    int *dstN;
    cudaGetSymbolAddress((void**)&whi,   g_w_hi);
    cudaGetSymbolAddress((void**)&wlo,   g_w_lo);
    cudaGetSymbolAddress((void**)&hhi,   g_h_hi);
    cudaGetSymbolAddress((void**)&hlo,   g_h_lo);
    cudaGetSymbolAddress((void**)&qkv,   g_qkv);
    cudaGetSymbolAddress((void**)&ahi,   g_attn_hi);
    cudaGetSymbolAddress((void**)&alo,   g_attn_lo);
    cudaGetSymbolAddress((void**)&t,     g_t);
    cudaGetSymbolAddress((void**)&h1,    g_h1);
    cudaGetSymbolAddress((void**)&h1hi,  g_h1_hi);
    cudaGetSymbolAddress((void**)&h1lo,  g_h1_lo);
    cudaGetSymbolAddress((void**)&acthi, g_act_hi);
    cudaGetSymbolAddress((void**)&actlo, g_act_lo);
    cudaGetSymbolAddress((void**)&dstN,  g_dst);

    // dst normalize (int32 vs silently-int64)
    detect_dst_kernel<<<1, 256>>>(dstR);
    normalize_dst_kernel<<<EE / 256, 256>>>(dstR);

    // bf16 splits: weights + h
    split_kernel<<<64,  256>>>(Wq, whi + WQ_OFF, wlo + WQ_OFF, 65536);
    split_kernel<<<64,  256>>>(Wk, whi + WK_OFF, wlo + WK_OFF, 65536);
    split_kernel<<<64,  256>>>(Wv, whi + WV_OFF, wlo + WV_OFF, 65536);
    split_kernel<<<64,  256>>>(Wo, whi + WO_OFF, wlo + WO_OFF, 65536);
    split_kernel<<<256, 256>>>(W1, whi + W1_OFF, wlo + W1_OFF, 262144);
    split_kernel<<<256, 256>>>(W2, whi + W2_OFF, wlo + W2_OFF, 262144);
    split_kernel<<<NN * DD / 1024, 256>>>(h, hhi, hlo, NN * DD);

    dim3 gQKV(DD / 64, NN / 128, 3);
    dim3 gD(DD / 64, NN / 128);
    dim3 gF(FF / 64, NN / 128);

    // QKV (tensor cores, fused 3-in-1 launch)
    qkv_wmma_kernel<<<gQKV, 256, SM_BYTES>>>(hhi, hlo, bq, bk, bv, qkv);

    // attention (emits bf16 split)
    attn_kernel<<<NN, 128>>>(qkv, qkv + NN * DD, qkv + 2 * NN * DD, ew, dstN, ahi, alo);

    // O-proj
    gemm_wmma_kernel<0><<<gD, 256, SM_BYTES>>>(ahi, alo, whi + WO_OFF, wlo + WO_OFF,
                                               bo, t, nullptr, nullptr, DD, DD);
    add_ln_kernel<<<NN, 256>>>(t, h, l1g, l1b, h1, h1hi, h1lo);

    // FFN1 (relu, emits bf16 split act)
    gemm_wmma_kernel<1><<<gF, 256, SM_BYTES>>>(h1hi, h1lo, whi + W1_OFF, wlo + W1_OFF,
                                               b1, nullptr, acthi, actlo, FF, DD);
    // FFN2 (K=1024)
    gemm_wmma_kernel<0><<<gD, 256, SM_BYTES>>>(acthi, actlo, whi + W2_OFF, wlo + W2_OFF,
                                               b2, t, nullptr, nullptr, DD, FF);
    add_ln_kernel<<<NN, 256>>>(t, h1, l2g, l2b, (float*)d_out, nullptr, nullptr);
}